// round 9
// baseline (speedup 1.0000x reference)
#include <cuda_runtime.h>
#include <cuda_fp16.h>
#include <cstdint>

#define DH 64
#define BM 128
#define BN 64
#define SKB 144          // smem row stride bytes (72 fp16) -> ldmatrix conflict-free

#define SM_QH  0
#define SM_KH  (BM*SKB)               // 18432
#define SM_VH  (SM_KH + BN*SKB)       // 27648
#define SM_TOTAL (SM_VH + BN*SKB)     // 36864 B

#define MAXROWS 16384
#define NCH_MAX 4

__device__ float g_Opart[(size_t)NCH_MAX * MAXROWS * DH];
__device__ float g_lpart[(size_t)NCH_MAX * MAXROWS];

static __device__ __forceinline__ uint32_t smem_u32(const void* p){
    uint32_t a;
    asm("{ .reg .u64 t; cvta.to.shared.u64 t, %1; cvt.u32.u64 %0, t; }" : "=r"(a) : "l"(p));
    return a;
}
static __device__ __forceinline__ uint32_t pkh(__half a, __half b){
    __half2 t = __halves2half2(a, b);
    return *reinterpret_cast<uint32_t*>(&t);
}
static __device__ __forceinline__ float ex2f(float x){
    float r;
    asm("ex2.approx.f32 %0, %1;" : "=f"(r) : "f"(x));
    return r;
}
// 8 floats -> 8 fp16
static __device__ __forceinline__ void cvtH8(const float* f, uint4& out){
    uint32_t r[4];
    #pragma unroll
    for (int i = 0; i < 4; i++){
        __half2 h = __floats2half2_rn(f[2*i], f[2*i+1]);
        r[i] = *reinterpret_cast<uint32_t*>(&h);
    }
    out = make_uint4(r[0], r[1], r[2], r[3]);
}
static __device__ __forceinline__ void ldsm4(uint32_t* r, uint32_t a){
    asm volatile("ldmatrix.sync.aligned.m8n8.x4.shared.b16 {%0,%1,%2,%3}, [%4];"
                 : "=r"(r[0]), "=r"(r[1]), "=r"(r[2]), "=r"(r[3]) : "r"(a));
}
static __device__ __forceinline__ void ldsm4t(uint32_t* r, uint32_t a){
    asm volatile("ldmatrix.sync.aligned.m8n8.x4.trans.shared.b16 {%0,%1,%2,%3}, [%4];"
                 : "=r"(r[0]), "=r"(r[1]), "=r"(r[2]), "=r"(r[3]) : "r"(a));
}
static __device__ __forceinline__ void mma16816(float* d, const uint32_t* a, uint32_t b0, uint32_t b1){
    asm volatile("mma.sync.aligned.m16n8k16.row.col.f32.f16.f16.f32 "
                 "{%0,%1,%2,%3}, {%4,%5,%6,%7}, {%8,%9}, {%0,%1,%2,%3};"
                 : "+f"(d[0]), "+f"(d[1]), "+f"(d[2]), "+f"(d[3])
                 : "r"(a[0]), "r"(a[1]), "r"(a[2]), "r"(a[3]), "r"(b0), "r"(b1));
}

// ---------------- Phase 1: partial attention over one key chunk ----------------
__global__ __launch_bounds__(256, 1)
void fa_part_kernel(const float* __restrict__ Q, const float* __restrict__ K,
                    const float* __restrict__ V, const int* __restrict__ vlen,
                    int Lq, int Lk, int ck)
{
    extern __shared__ char smem[];
    const uint32_t sb = smem_u32(smem);
    const int t  = threadIdx.x;
    const int w  = t >> 5;
    const int ln = t & 31;
    const int g  = ln >> 2;
    const int tg = ln & 3;
    const int b  = blockIdx.y;
    const int q0 = blockIdx.x * BM;
    const int c  = blockIdx.z;

    int vl = vlen[b];
    if (vl < 1) vl = 1;
    if (vl > Lk) vl = Lk;

    const int cstart = c * ck;
    if (cstart >= vl) return;
    const int kend   = (cstart + ck < vl) ? cstart + ck : vl;
    const int ntiles = (kend - cstart + BN - 1) / BN;

    const int B_ = gridDim.y;
    const int R  = B_ * Lq;

    const float* Qb = Q + ((size_t)b * Lq + q0) * DH;
    const float* Kb = K + ((size_t)b * Lk + cstart) * DH;
    const float* Vb = V + ((size_t)b * Lk + cstart) * DH;

    // ---- Q -> smem, pre-scaled by log2e/sqrt(d), single fp16 ----
    {
        int r = t >> 1, h = t & 1;
        const float* qp = Qb + (size_t)r * DH + h * 32;
        float f[32];
        #pragma unroll
        for (int i = 0; i < 8; i++) *(float4*)(f + 4*i) = *(const float4*)(qp + 4*i);
        #pragma unroll
        for (int i = 0; i < 32; i++) f[i] *= 0.18033688f;   // 1.4426950f / 8
        #pragma unroll
        for (int cc = 0; cc < 4; cc++){
            uint4 u; cvtH8(f + 8*cc, u);
            *(uint4*)(smem + SM_QH + r * SKB + (h*4 + cc) * 16) = u;
        }
    }
    __syncthreads();

    // ---- Q A-fragments (registers for whole kernel) ----
    uint32_t qh[4][4];
    {
        uint32_t rowoff = (uint32_t)(16*w + (ln & 15)) * SKB + (uint32_t)(ln >> 4) * 16;
        #pragma unroll
        for (int ks = 0; ks < 4; ks++)
            ldsm4(qh[ks], sb + SM_QH + rowoff + ks * 32);
    }

    float oc[8][4];
    #pragma unroll
    for (int nt = 0; nt < 8; nt++)
        #pragma unroll
        for (int j = 0; j < 4; j++) oc[nt][j] = 0.f;
    float lsum0 = 0.f, lsum1 = 0.f;

    // ---- prefetch tile 0 ----
    const int r4 = t >> 2, qq = t & 3;
    float4 kf[4], vf[4];
    {
        const float* kp = Kb + (size_t)r4 * DH + qq * 16;
        const float* vp = Vb + (size_t)r4 * DH + qq * 16;
        #pragma unroll
        for (int i = 0; i < 4; i++){ kf[i] = *(const float4*)(kp + 4*i); vf[i] = *(const float4*)(vp + 4*i); }
    }

    for (int kt = 0; kt < ntiles; kt++){
        const int n0g = cstart + kt * BN;

        __syncthreads();   // prev tile's ldmatrix reads done
        // ---- store K/V tile as single fp16 ----
        {
            int off = r4 * SKB + qq * 32;
            float fk[8];
            uint4 u;
            *(float4*)(fk)   = kf[0]; *(float4*)(fk+4) = kf[1];
            cvtH8(fk, u); *(uint4*)(smem + SM_KH + off) = u;
            *(float4*)(fk)   = kf[2]; *(float4*)(fk+4) = kf[3];
            cvtH8(fk, u); *(uint4*)(smem + SM_KH + off + 16) = u;
            *(float4*)(fk)   = vf[0]; *(float4*)(fk+4) = vf[1];
            cvtH8(fk, u); *(uint4*)(smem + SM_VH + off) = u;
            *(float4*)(fk)   = vf[2]; *(float4*)(fk+4) = vf[3];
            cvtH8(fk, u); *(uint4*)(smem + SM_VH + off + 16) = u;
        }
        __syncthreads();

        // ---- prefetch next tile ----
        if (kt + 1 < ntiles){
            const float* kp = Kb + (size_t)((kt+1)*BN + r4) * DH + qq * 16;
            const float* vp = Vb + (size_t)((kt+1)*BN + r4) * DH + qq * 16;
            #pragma unroll
            for (int i = 0; i < 4; i++){ kf[i] = *(const float4*)(kp + 4*i); vf[i] = *(const float4*)(vp + 4*i); }
        }

        // ---- S(log2 domain) = qh * kh : single pass ----
        float sc[8][4];
        #pragma unroll
        for (int nt = 0; nt < 8; nt++){
            #pragma unroll
            for (int j = 0; j < 4; j++) sc[nt][j] = 0.f;
            uint32_t kh[8];
            uint32_t base = (uint32_t)(8*nt + (ln & 7)) * SKB
                          + (uint32_t)((ln >> 3) & 1) * 16
                          + (uint32_t)(ln >> 4) * 32;
            ldsm4(kh + 0, sb + SM_KH + base);
            ldsm4(kh + 4, sb + SM_KH + base + 64);
            #pragma unroll
            for (int ks = 0; ks < 4; ks++)
                mma16816(sc[nt], qh[ks], kh[2*ks], kh[2*ks+1]);
        }

        // ---- P = 2^S ; exact split p = ph + pl ----
        uint32_t phi[4][4], plo[4][4];
        if (n0g + BN <= vl){
            // fast path: all 64 keys valid, no mask compares
            #pragma unroll
            for (int nt = 0; nt < 8; nt++){
                float e0 = ex2f(sc[nt][0]);
                float e1 = ex2f(sc[nt][1]);
                float e2 = ex2f(sc[nt][2]);
                float e3 = ex2f(sc[nt][3]);
                lsum0 += e0 + e1;
                lsum1 += e2 + e3;
                __half h0 = __float2half_rn(e0), h1 = __float2half_rn(e1);
                __half h2 = __float2half_rn(e2), h3 = __float2half_rn(e3);
                __half x0 = __float2half_rn(e0 - __half2float(h0));
                __half x1 = __float2half_rn(e1 - __half2float(h1));
                __half x2 = __float2half_rn(e2 - __half2float(h2));
                __half x3 = __float2half_rn(e3 - __half2float(h3));
                int j = nt >> 1, hf = (nt & 1) * 2;
                phi[j][hf + 0] = pkh(h0, h1); phi[j][hf + 1] = pkh(h2, h3);
                plo[j][hf + 0] = pkh(x0, x1); plo[j][hf + 1] = pkh(x2, x3);
            }
        } else {
            #pragma unroll
            for (int nt = 0; nt < 8; nt++){
                int c0 = n0g + nt*8 + 2*tg;
                float e0 = (c0     < vl) ? ex2f(sc[nt][0]) : 0.f;
                float e1 = (c0 + 1 < vl) ? ex2f(sc[nt][1]) : 0.f;
                float e2 = (c0     < vl) ? ex2f(sc[nt][2]) : 0.f;
                float e3 = (c0 + 1 < vl) ? ex2f(sc[nt][3]) : 0.f;
                lsum0 += e0 + e1;
                lsum1 += e2 + e3;
                __half h0 = __float2half_rn(e0), h1 = __float2half_rn(e1);
                __half h2 = __float2half_rn(e2), h3 = __float2half_rn(e3);
                __half x0 = __float2half_rn(e0 - __half2float(h0));
                __half x1 = __float2half_rn(e1 - __half2float(h1));
                __half x2 = __float2half_rn(e2 - __half2float(h2));
                __half x3 = __float2half_rn(e3 - __half2float(h3));
                int j = nt >> 1, hf = (nt & 1) * 2;
                phi[j][hf + 0] = pkh(h0, h1); phi[j][hf + 1] = pkh(h2, h3);
                plo[j][hf + 0] = pkh(x0, x1); plo[j][hf + 1] = pkh(x2, x3);
            }
        }

        // ---- O += (ph + pl) * vh : 2 passes, vh read once ----
        #pragma unroll
        for (int nt = 0; nt < 8; nt++){
            uint32_t vh[8];
            uint32_t base = (uint32_t)ln * SKB + (uint32_t)nt * 16;
            ldsm4t(vh + 0, sb + SM_VH + base);
            ldsm4t(vh + 4, sb + SM_VH + base + 32u * SKB);
            #pragma unroll
            for (int ks = 0; ks < 4; ks++){
                mma16816(oc[nt], phi[ks], vh[2*ks], vh[2*ks+1]);
                mma16816(oc[nt], plo[ks], vh[2*ks], vh[2*ks+1]);
            }
        }
    }

    // ---- reduce row sums across quads ----
    lsum0 += __shfl_xor_sync(0xffffffffu, lsum0, 1);
    lsum0 += __shfl_xor_sync(0xffffffffu, lsum0, 2);
    lsum1 += __shfl_xor_sync(0xffffffffu, lsum1, 1);
    lsum1 += __shfl_xor_sync(0xffffffffu, lsum1, 2);

    // ---- write unnormalized partials to scratch ----
    const int rg0 = b * Lq + q0 + 16*w + g;
    float* Op0 = g_Opart + ((size_t)c * R + rg0) * DH;
    float* Op1 = Op0 + (size_t)8 * DH;
    if (tg == 0){
        g_lpart[(size_t)c * R + rg0]     = lsum0;
        g_lpart[(size_t)c * R + rg0 + 8] = lsum1;
    }
    #pragma unroll
    for (int nt = 0; nt < 8; nt++){
        float2 a0, a1;
        a0.x = oc[nt][0]; a0.y = oc[nt][1];
        a1.x = oc[nt][2]; a1.y = oc[nt][3];
        *(float2*)(Op0 + nt*8 + 2*tg) = a0;
        *(float2*)(Op1 + nt*8 + 2*tg) = a1;
    }
}

// ---------------- Phase 2: combine chunk partials + normalize ----------------
// One thread owns 8 output floats -> 8 float4 + 4 scalar loads in flight.
__global__ __launch_bounds__(256, 8)
void fa_combine_kernel(const int* __restrict__ vlen, float* __restrict__ O,
                       int Lq, int Lk, int B, int ck)
{
    const int idx = blockIdx.x * blockDim.x + threadIdx.x;
    const int total = B * Lq * (DH / 8);
    if (idx >= total) return;

    const int rd = idx >> 3;        // global row (b*Lq + q)
    const int d8 = (idx & 7) * 8;   // starting d
    const int b  = rd / Lq;
    const int R  = B * Lq;

    int vl = vlen[b];
    if (vl < 1) vl = 1;
    if (vl > Lk) vl = Lk;
    const int nact = (vl + ck - 1) / ck;

    float4 p0[NCH_MAX], p1[NCH_MAX];
    float  lp[NCH_MAX];
    #pragma unroll
    for (int c = 0; c < NCH_MAX; c++){
        const float* base = g_Opart + ((size_t)c * R + rd) * DH + d8;
        p0[c] = *(const float4*)(base);
        p1[c] = *(const float4*)(base + 4);
        lp[c] = g_lpart[(size_t)c * R + rd];
    }
    float4 a0 = make_float4(0.f, 0.f, 0.f, 0.f);
    float4 a1 = make_float4(0.f, 0.f, 0.f, 0.f);
    float l = 0.f;
    #pragma unroll
    for (int c = 0; c < NCH_MAX; c++){
        const bool v = (c < nact);
        a0.x += v ? p0[c].x : 0.f;  a0.y += v ? p0[c].y : 0.f;
        a0.z += v ? p0[c].z : 0.f;  a0.w += v ? p0[c].w : 0.f;
        a1.x += v ? p1[c].x : 0.f;  a1.y += v ? p1[c].y : 0.f;
        a1.z += v ? p1[c].z : 0.f;  a1.w += v ? p1[c].w : 0.f;
        l    += v ? lp[c]  : 0.f;
    }
    const float inv = 1.f / l;
    a0.x *= inv; a0.y *= inv; a0.z *= inv; a0.w *= inv;
    a1.x *= inv; a1.y *= inv; a1.z *= inv; a1.w *= inv;
    float* out = O + (size_t)rd * DH + d8;
    *(float4*)(out)     = a0;
    *(float4*)(out + 4) = a1;
}

extern "C" void kernel_launch(void* const* d_in, const int* in_sizes, int n_in,
                              void* d_out, int out_size)
{
    const float* Q  = (const float*)d_in[0];
    const float* K  = (const float*)d_in[1];
    const float* V  = (const float*)d_in[2];
    const int*   vl = (const int*)d_in[3];
    float*       O  = (float*)d_out;

    const int B  = in_sizes[3];
    const int Lq = in_sizes[0] / (B * DH);
    const int Lk = in_sizes[1] / (B * DH);

    int ck = ((Lk + NCH_MAX * BN - 1) / (NCH_MAX * BN)) * BN;
    if (ck < BN) ck = BN;
    const int nch = (Lk + ck - 1) / ck;

    cudaFuncSetAttribute(fa_part_kernel,
                         cudaFuncAttributeMaxDynamicSharedMemorySize, SM_TOTAL);

    dim3 grid1(Lq / BM, B, nch);
    fa_part_kernel<<<grid1, 256, SM_TOTAL>>>(Q, K, V, vl, Lq, Lk, ck);

    const int total = B * Lq * (DH / 8);
    fa_combine_kernel<<<(total + 255) / 256, 256>>>(vl, O, Lq, Lk, B, ck);
}

// round 10
// speedup vs baseline: 1.1154x; 1.1154x over previous
#include <cuda_runtime.h>
#include <cuda_fp16.h>
#include <cstdint>

#define DH 64
#define BM 128
#define BN 64
#define SKB 144          // smem row stride bytes (72 fp16) -> ldmatrix conflict-free

#define SM_QH  0
#define SM_KH  (BM*SKB)               // 18432
#define SM_VH  (SM_KH + BN*SKB)       // 27648
#define SM_TOTAL (SM_VH + BN*SKB)     // 36864 B

#define MAXROWS 16384
#define NCH_MAX 4

__device__ float g_Opart[(size_t)NCH_MAX * MAXROWS * DH];
__device__ float g_lpart[(size_t)NCH_MAX * MAXROWS];

static __device__ __forceinline__ uint32_t smem_u32(const void* p){
    uint32_t a;
    asm("{ .reg .u64 t; cvta.to.shared.u64 t, %1; cvt.u32.u64 %0, t; }" : "=r"(a) : "l"(p));
    return a;
}
static __device__ __forceinline__ float ex2f(float x){
    float r;
    asm("ex2.approx.f32 %0, %1;" : "=f"(r) : "f"(x));
    return r;
}
static __device__ __forceinline__ uint32_t cvt2h(float a, float b){
    __half2 h = __floats2half2_rn(a, b);
    return *reinterpret_cast<uint32_t*>(&h);
}
// 8 floats -> 8 fp16
static __device__ __forceinline__ void cvtH8(const float* f, uint4& out){
    out = make_uint4(cvt2h(f[0], f[1]), cvt2h(f[2], f[3]),
                     cvt2h(f[4], f[5]), cvt2h(f[6], f[7]));
}
static __device__ __forceinline__ void ldsm4(uint32_t* r, uint32_t a){
    asm volatile("ldmatrix.sync.aligned.m8n8.x4.shared.b16 {%0,%1,%2,%3}, [%4];"
                 : "=r"(r[0]), "=r"(r[1]), "=r"(r[2]), "=r"(r[3]) : "r"(a));
}
static __device__ __forceinline__ void ldsm4t(uint32_t* r, uint32_t a){
    asm volatile("ldmatrix.sync.aligned.m8n8.x4.trans.shared.b16 {%0,%1,%2,%3}, [%4];"
                 : "=r"(r[0]), "=r"(r[1]), "=r"(r[2]), "=r"(r[3]) : "r"(a));
}
static __device__ __forceinline__ void mma16816(float* d, const uint32_t* a, uint32_t b0, uint32_t b1){
    asm volatile("mma.sync.aligned.m16n8k16.row.col.f32.f16.f16.f32 "
                 "{%0,%1,%2,%3}, {%4,%5,%6,%7}, {%8,%9}, {%0,%1,%2,%3};"
                 : "+f"(d[0]), "+f"(d[1]), "+f"(d[2]), "+f"(d[3])
                 : "r"(a[0]), "r"(a[1]), "r"(a[2]), "r"(a[3]), "r"(b0), "r"(b1));
}

// ---------------- Phase 1: partial attention over one key chunk ----------------
__global__ __launch_bounds__(256, 1)
void fa_part_kernel(const float* __restrict__ Q, const float* __restrict__ K,
                    const float* __restrict__ V, const int* __restrict__ vlen,
                    int Lq, int Lk, int ck)
{
    extern __shared__ char smem[];
    const uint32_t sb = smem_u32(smem);
    const int t  = threadIdx.x;
    const int w  = t >> 5;
    const int ln = t & 31;
    const int g  = ln >> 2;
    const int tg = ln & 3;
    const int b  = blockIdx.y;
    const int q0 = blockIdx.x * BM;
    const int c  = blockIdx.z;

    int vl = vlen[b];
    if (vl < 1) vl = 1;
    if (vl > Lk) vl = Lk;

    const int cstart = c * ck;
    if (cstart >= vl) return;
    const int kend   = (cstart + ck < vl) ? cstart + ck : vl;
    const int ntiles = (kend - cstart + BN - 1) / BN;

    const int B_ = gridDim.y;
    const int R  = B_ * Lq;

    const float* Qb = Q + ((size_t)b * Lq + q0) * DH;
    const float* Kb = K + ((size_t)b * Lk + cstart) * DH;
    const float* Vb = V + ((size_t)b * Lk + cstart) * DH;

    // ---- Q -> smem, pre-scaled by log2e/sqrt(d), single fp16 ----
    {
        int r = t >> 1, h = t & 1;
        const float* qp = Qb + (size_t)r * DH + h * 32;
        float f[32];
        #pragma unroll
        for (int i = 0; i < 8; i++) *(float4*)(f + 4*i) = *(const float4*)(qp + 4*i);
        #pragma unroll
        for (int i = 0; i < 32; i++) f[i] *= 0.18033688f;   // 1.4426950f / 8
        #pragma unroll
        for (int cc = 0; cc < 4; cc++){
            uint4 u; cvtH8(f + 8*cc, u);
            *(uint4*)(smem + SM_QH + r * SKB + (h*4 + cc) * 16) = u;
        }
    }
    __syncthreads();

    // ---- Q A-fragments (registers for whole kernel) ----
    uint32_t qh[4][4];
    {
        uint32_t rowoff = (uint32_t)(16*w + (ln & 15)) * SKB + (uint32_t)(ln >> 4) * 16;
        #pragma unroll
        for (int ks = 0; ks < 4; ks++)
            ldsm4(qh[ks], sb + SM_QH + rowoff + ks * 32);
    }

    float oc[8][4];
    #pragma unroll
    for (int nt = 0; nt < 8; nt++)
        #pragma unroll
        for (int j = 0; j < 4; j++) oc[nt][j] = 0.f;
    float lsum0 = 0.f, lsum1 = 0.f;

    // ---- prefetch tile 0 ----
    const int r4 = t >> 2, qq = t & 3;
    float4 kf[4], vf[4];
    {
        const float* kp = Kb + (size_t)r4 * DH + qq * 16;
        const float* vp = Vb + (size_t)r4 * DH + qq * 16;
        #pragma unroll
        for (int i = 0; i < 4; i++){ kf[i] = *(const float4*)(kp + 4*i); vf[i] = *(const float4*)(vp + 4*i); }
    }

    for (int kt = 0; kt < ntiles; kt++){
        const int n0g = cstart + kt * BN;

        __syncthreads();   // prev tile's ldmatrix reads done
        // ---- store K/V tile as single fp16 ----
        {
            int off = r4 * SKB + qq * 32;
            float fk[8];
            uint4 u;
            *(float4*)(fk)   = kf[0]; *(float4*)(fk+4) = kf[1];
            cvtH8(fk, u); *(uint4*)(smem + SM_KH + off) = u;
            *(float4*)(fk)   = kf[2]; *(float4*)(fk+4) = kf[3];
            cvtH8(fk, u); *(uint4*)(smem + SM_KH + off + 16) = u;
            *(float4*)(fk)   = vf[0]; *(float4*)(fk+4) = vf[1];
            cvtH8(fk, u); *(uint4*)(smem + SM_VH + off) = u;
            *(float4*)(fk)   = vf[2]; *(float4*)(fk+4) = vf[3];
            cvtH8(fk, u); *(uint4*)(smem + SM_VH + off + 16) = u;
        }
        __syncthreads();

        // ---- prefetch next tile ----
        if (kt + 1 < ntiles){
            const float* kp = Kb + (size_t)((kt+1)*BN + r4) * DH + qq * 16;
            const float* vp = Vb + (size_t)((kt+1)*BN + r4) * DH + qq * 16;
            #pragma unroll
            for (int i = 0; i < 4; i++){ kf[i] = *(const float4*)(kp + 4*i); vf[i] = *(const float4*)(vp + 4*i); }
        }

        // ---- S(log2 domain) = qh * kh : single pass ----
        float sc[8][4];
        #pragma unroll
        for (int nt = 0; nt < 8; nt++){
            #pragma unroll
            for (int j = 0; j < 4; j++) sc[nt][j] = 0.f;
            uint32_t kh[8];
            uint32_t base = (uint32_t)(8*nt + (ln & 7)) * SKB
                          + (uint32_t)((ln >> 3) & 1) * 16
                          + (uint32_t)(ln >> 4) * 32;
            ldsm4(kh + 0, sb + SM_KH + base);
            ldsm4(kh + 4, sb + SM_KH + base + 64);
            #pragma unroll
            for (int ks = 0; ks < 4; ks++)
                mma16816(sc[nt], qh[ks], kh[2*ks], kh[2*ks+1]);
        }

        // ---- P = 2^S, single fp16 (no split) ----
        uint32_t phi[4][4];
        if (n0g + BN <= vl){
            // fast path: all 64 keys valid
            #pragma unroll
            for (int nt = 0; nt < 8; nt++){
                float e0 = ex2f(sc[nt][0]);
                float e1 = ex2f(sc[nt][1]);
                float e2 = ex2f(sc[nt][2]);
                float e3 = ex2f(sc[nt][3]);
                lsum0 += e0 + e1;
                lsum1 += e2 + e3;
                int j = nt >> 1, hf = (nt & 1) * 2;
                phi[j][hf + 0] = cvt2h(e0, e1);
                phi[j][hf + 1] = cvt2h(e2, e3);
            }
        } else {
            #pragma unroll
            for (int nt = 0; nt < 8; nt++){
                int c0 = n0g + nt*8 + 2*tg;
                float e0 = (c0     < vl) ? ex2f(sc[nt][0]) : 0.f;
                float e1 = (c0 + 1 < vl) ? ex2f(sc[nt][1]) : 0.f;
                float e2 = (c0     < vl) ? ex2f(sc[nt][2]) : 0.f;
                float e3 = (c0 + 1 < vl) ? ex2f(sc[nt][3]) : 0.f;
                lsum0 += e0 + e1;
                lsum1 += e2 + e3;
                int j = nt >> 1, hf = (nt & 1) * 2;
                phi[j][hf + 0] = cvt2h(e0, e1);
                phi[j][hf + 1] = cvt2h(e2, e3);
            }
        }

        // ---- O += ph * vh : single pass ----
        #pragma unroll
        for (int nt = 0; nt < 8; nt++){
            uint32_t vh[8];
            uint32_t base = (uint32_t)ln * SKB + (uint32_t)nt * 16;
            ldsm4t(vh + 0, sb + SM_VH + base);
            ldsm4t(vh + 4, sb + SM_VH + base + 32u * SKB);
            #pragma unroll
            for (int ks = 0; ks < 4; ks++)
                mma16816(oc[nt], phi[ks], vh[2*ks], vh[2*ks+1]);
        }
    }

    // ---- reduce row sums across quads ----
    lsum0 += __shfl_xor_sync(0xffffffffu, lsum0, 1);
    lsum0 += __shfl_xor_sync(0xffffffffu, lsum0, 2);
    lsum1 += __shfl_xor_sync(0xffffffffu, lsum1, 1);
    lsum1 += __shfl_xor_sync(0xffffffffu, lsum1, 2);

    // ---- write unnormalized partials to scratch ----
    const int rg0 = b * Lq + q0 + 16*w + g;
    float* Op0 = g_Opart + ((size_t)c * R + rg0) * DH;
    float* Op1 = Op0 + (size_t)8 * DH;
    if (tg == 0){
        g_lpart[(size_t)c * R + rg0]     = lsum0;
        g_lpart[(size_t)c * R + rg0 + 8] = lsum1;
    }
    #pragma unroll
    for (int nt = 0; nt < 8; nt++){
        float2 a0, a1;
        a0.x = oc[nt][0]; a0.y = oc[nt][1];
        a1.x = oc[nt][2]; a1.y = oc[nt][3];
        *(float2*)(Op0 + nt*8 + 2*tg) = a0;
        *(float2*)(Op1 + nt*8 + 2*tg) = a1;
    }
}

// ---------------- Phase 2: combine chunk partials + normalize ----------------
// (R8 shape: 16 threads per row, 4 float4 + 4 scalar loads in flight)
__global__ __launch_bounds__(256, 8)
void fa_combine_kernel(const int* __restrict__ vlen, float* __restrict__ O,
                       int Lq, int Lk, int B, int ck)
{
    const int idx = blockIdx.x * blockDim.x + threadIdx.x;
    const int total = B * Lq * (DH / 4);
    if (idx >= total) return;

    const int rd = idx >> 4;
    const int d4 = idx & 15;
    const int b  = rd / Lq;
    const int R  = B * Lq;

    int vl = vlen[b];
    if (vl < 1) vl = 1;
    if (vl > Lk) vl = Lk;
    const int nact = (vl + ck - 1) / ck;

    float4 p[NCH_MAX];
    float  lp[NCH_MAX];
    #pragma unroll
    for (int c = 0; c < NCH_MAX; c++){
        p[c]  = *(const float4*)(g_Opart + ((size_t)c * R + rd) * DH + d4 * 4);
        lp[c] = g_lpart[(size_t)c * R + rd];
    }
    float4 acc = make_float4(0.f, 0.f, 0.f, 0.f);
    float l = 0.f;
    #pragma unroll
    for (int c = 0; c < NCH_MAX; c++){
        const bool v = (c < nact);
        acc.x += v ? p[c].x : 0.f;
        acc.y += v ? p[c].y : 0.f;
        acc.z += v ? p[c].z : 0.f;
        acc.w += v ? p[c].w : 0.f;
        l     += v ? lp[c]  : 0.f;
    }
    const float inv = 1.f / l;
    acc.x *= inv; acc.y *= inv; acc.z *= inv; acc.w *= inv;
    *(float4*)(O + (size_t)rd * DH + d4 * 4) = acc;
}

extern "C" void kernel_launch(void* const* d_in, const int* in_sizes, int n_in,
                              void* d_out, int out_size)
{
    const float* Q  = (const float*)d_in[0];
    const float* K  = (const float*)d_in[1];
    const float* V  = (const float*)d_in[2];
    const int*   vl = (const int*)d_in[3];
    float*       O  = (float*)d_out;

    const int B  = in_sizes[3];
    const int Lq = in_sizes[0] / (B * DH);
    const int Lk = in_sizes[1] / (B * DH);

    int ck = ((Lk + NCH_MAX * BN - 1) / (NCH_MAX * BN)) * BN;
    if (ck < BN) ck = BN;
    const int nch = (Lk + ck - 1) / ck;

    cudaFuncSetAttribute(fa_part_kernel,
                         cudaFuncAttributeMaxDynamicSharedMemorySize, SM_TOTAL);

    dim3 grid1(Lq / BM, B, nch);
    fa_part_kernel<<<grid1, 256, SM_TOTAL>>>(Q, K, V, vl, Lq, Lk, ck);

    const int total = B * Lq * (DH / 4);
    fa_combine_kernel<<<(total + 255) / 256, 256>>>(vl, O, Lq, Lk, B, ck);
}

// round 11
// speedup vs baseline: 1.3215x; 1.1848x over previous
#include <cuda_runtime.h>
#include <cuda_fp16.h>
#include <cstdint>

#define DH 64
#define BM 128
#define BN 64
#define SKB 144          // smem row stride bytes (72 fp16) -> ldmatrix conflict-free

#define SM_QH  0
#define SM_KH  (BM*SKB)               // 18432
#define SM_VH  (SM_KH + BN*SKB)       // 27648
#define SM_TOTAL (SM_VH + BN*SKB)     // 36864 B

#define MAXROWS 16384                 // max B*Lq and B*Lk
#define NCH_MAX 4

__device__ float g_Opart[(size_t)NCH_MAX * MAXROWS * DH];
__device__ float g_lpart[(size_t)NCH_MAX * MAXROWS];
// fp16 copies of K and V (filled by prepass, read by phase 1)
__device__ uint4 g_Kh[(size_t)MAXROWS * DH / 8];
__device__ uint4 g_Vh[(size_t)MAXROWS * DH / 8];

static __device__ __forceinline__ uint32_t smem_u32(const void* p){
    uint32_t a;
    asm("{ .reg .u64 t; cvta.to.shared.u64 t, %1; cvt.u32.u64 %0, t; }" : "=r"(a) : "l"(p));
    return a;
}
static __device__ __forceinline__ float ex2f(float x){
    float r;
    asm("ex2.approx.f32 %0, %1;" : "=f"(r) : "f"(x));
    return r;
}
static __device__ __forceinline__ uint32_t cvt2h(float a, float b){
    __half2 h = __floats2half2_rn(a, b);
    return *reinterpret_cast<uint32_t*>(&h);
}
static __device__ __forceinline__ void cvtH8(const float* f, uint4& out){
    out = make_uint4(cvt2h(f[0], f[1]), cvt2h(f[2], f[3]),
                     cvt2h(f[4], f[5]), cvt2h(f[6], f[7]));
}
static __device__ __forceinline__ void ldsm4(uint32_t* r, uint32_t a){
    asm volatile("ldmatrix.sync.aligned.m8n8.x4.shared.b16 {%0,%1,%2,%3}, [%4];"
                 : "=r"(r[0]), "=r"(r[1]), "=r"(r[2]), "=r"(r[3]) : "r"(a));
}
static __device__ __forceinline__ void ldsm4t(uint32_t* r, uint32_t a){
    asm volatile("ldmatrix.sync.aligned.m8n8.x4.trans.shared.b16 {%0,%1,%2,%3}, [%4];"
                 : "=r"(r[0]), "=r"(r[1]), "=r"(r[2]), "=r"(r[3]) : "r"(a));
}
static __device__ __forceinline__ void mma16816(float* d, const uint32_t* a, uint32_t b0, uint32_t b1){
    asm volatile("mma.sync.aligned.m16n8k16.row.col.f32.f16.f16.f32 "
                 "{%0,%1,%2,%3}, {%4,%5,%6,%7}, {%8,%9}, {%0,%1,%2,%3};"
                 : "+f"(d[0]), "+f"(d[1]), "+f"(d[2]), "+f"(d[3])
                 : "r"(a[0]), "r"(a[1]), "r"(a[2]), "r"(a[3]), "r"(b0), "r"(b1));
}

// ---------------- Phase 0: convert K,V fp32 -> fp16 once ----------------
__global__ __launch_bounds__(256, 8)
void fa_cvt_kernel(const float* __restrict__ K, const float* __restrict__ V, int n8)
{
    const int i = blockIdx.x * blockDim.x + threadIdx.x;
    if (i >= n8) return;
    float f[8];
    *(float4*)(f)     = *(const float4*)(K + (size_t)i * 8);
    *(float4*)(f + 4) = *(const float4*)(K + (size_t)i * 8 + 4);
    uint4 u; cvtH8(f, u);
    g_Kh[i] = u;
    *(float4*)(f)     = *(const float4*)(V + (size_t)i * 8);
    *(float4*)(f + 4) = *(const float4*)(V + (size_t)i * 8 + 4);
    cvtH8(f, u);
    g_Vh[i] = u;
}

// ---------------- Phase 1: partial attention over one key chunk ----------------
__global__ __launch_bounds__(256, 1)
void fa_part_kernel(const float* __restrict__ Q, const int* __restrict__ vlen,
                    int Lq, int Lk, int ck)
{
    extern __shared__ char smem[];
    const uint32_t sb = smem_u32(smem);
    const int t  = threadIdx.x;
    const int w  = t >> 5;
    const int ln = t & 31;
    const int g  = ln >> 2;
    const int tg = ln & 3;
    const int b  = blockIdx.y;
    const int q0 = blockIdx.x * BM;
    const int c  = blockIdx.z;

    int vl = vlen[b];
    if (vl < 1) vl = 1;
    if (vl > Lk) vl = Lk;

    const int cstart = c * ck;
    if (cstart >= vl) return;
    const int kend   = (cstart + ck < vl) ? cstart + ck : vl;
    const int ntiles = (kend - cstart + BN - 1) / BN;

    const int B_ = gridDim.y;
    const int R  = B_ * Lq;

    const float* Qb = Q + ((size_t)b * Lq + q0) * DH;
    // fp16 K/V rows (8 halfs per uint4 -> DH/8 = 8 uint4 per row)
    const uint4* Kb = g_Kh + ((size_t)b * Lk + cstart) * (DH / 8);
    const uint4* Vb = g_Vh + ((size_t)b * Lk + cstart) * (DH / 8);

    // ---- Q -> smem, pre-scaled by log2e/sqrt(d), single fp16 ----
    {
        int r = t >> 1, h = t & 1;
        const float* qp = Qb + (size_t)r * DH + h * 32;
        float f[32];
        #pragma unroll
        for (int i = 0; i < 8; i++) *(float4*)(f + 4*i) = *(const float4*)(qp + 4*i);
        #pragma unroll
        for (int i = 0; i < 32; i++) f[i] *= 0.18033688f;   // 1.4426950f / 8
        #pragma unroll
        for (int cc = 0; cc < 4; cc++){
            uint4 u; cvtH8(f + 8*cc, u);
            *(uint4*)(smem + SM_QH + r * SKB + (h*4 + cc) * 16) = u;
        }
    }
    __syncthreads();

    // ---- Q A-fragments (registers for whole kernel) ----
    uint32_t qh[4][4];
    {
        uint32_t rowoff = (uint32_t)(16*w + (ln & 15)) * SKB + (uint32_t)(ln >> 4) * 16;
        #pragma unroll
        for (int ks = 0; ks < 4; ks++)
            ldsm4(qh[ks], sb + SM_QH + rowoff + ks * 32);
    }

    float oc[8][4];
    #pragma unroll
    for (int nt = 0; nt < 8; nt++)
        #pragma unroll
        for (int j = 0; j < 4; j++) oc[nt][j] = 0.f;
    float lsum0 = 0.f, lsum1 = 0.f;

    // ---- prefetch tile 0: thread owns 32 halfs of K and of V ----
    const int r4 = t >> 2, qq = t & 3;       // row 0..63, 16-half chunk 0..3
    uint4 ku[2], vu[2];
    {
        const uint4* kp = Kb + (size_t)r4 * (DH / 8) + qq * 2;
        const uint4* vp = Vb + (size_t)r4 * (DH / 8) + qq * 2;
        ku[0] = kp[0]; ku[1] = kp[1];
        vu[0] = vp[0]; vu[1] = vp[1];
    }

    for (int kt = 0; kt < ntiles; kt++){
        const int n0g = cstart + kt * BN;

        __syncthreads();   // prev tile's ldmatrix reads done
        // ---- store K/V tile (raw fp16, no conversion) ----
        {
            int off = r4 * SKB + qq * 32;
            *(uint4*)(smem + SM_KH + off)      = ku[0];
            *(uint4*)(smem + SM_KH + off + 16) = ku[1];
            *(uint4*)(smem + SM_VH + off)      = vu[0];
            *(uint4*)(smem + SM_VH + off + 16) = vu[1];
        }
        __syncthreads();

        // ---- prefetch next tile ----
        if (kt + 1 < ntiles){
            const uint4* kp = Kb + (size_t)((kt+1)*BN + r4) * (DH / 8) + qq * 2;
            const uint4* vp = Vb + (size_t)((kt+1)*BN + r4) * (DH / 8) + qq * 2;
            ku[0] = kp[0]; ku[1] = kp[1];
            vu[0] = vp[0]; vu[1] = vp[1];
        }

        // ---- S(log2 domain) = qh * kh : single pass ----
        float sc[8][4];
        #pragma unroll
        for (int nt = 0; nt < 8; nt++){
            #pragma unroll
            for (int j = 0; j < 4; j++) sc[nt][j] = 0.f;
            uint32_t kh[8];
            uint32_t base = (uint32_t)(8*nt + (ln & 7)) * SKB
                          + (uint32_t)((ln >> 3) & 1) * 16
                          + (uint32_t)(ln >> 4) * 32;
            ldsm4(kh + 0, sb + SM_KH + base);
            ldsm4(kh + 4, sb + SM_KH + base + 64);
            #pragma unroll
            for (int ks = 0; ks < 4; ks++)
                mma16816(sc[nt], qh[ks], kh[2*ks], kh[2*ks+1]);
        }

        // ---- P = 2^S, single fp16 ----
        uint32_t phi[4][4];
        if (n0g + BN <= vl){
            #pragma unroll
            for (int nt = 0; nt < 8; nt++){
                float e0 = ex2f(sc[nt][0]);
                float e1 = ex2f(sc[nt][1]);
                float e2 = ex2f(sc[nt][2]);
                float e3 = ex2f(sc[nt][3]);
                lsum0 += e0 + e1;
                lsum1 += e2 + e3;
                int j = nt >> 1, hf = (nt & 1) * 2;
                phi[j][hf + 0] = cvt2h(e0, e1);
                phi[j][hf + 1] = cvt2h(e2, e3);
            }
        } else {
            #pragma unroll
            for (int nt = 0; nt < 8; nt++){
                int c0 = n0g + nt*8 + 2*tg;
                float e0 = (c0     < vl) ? ex2f(sc[nt][0]) : 0.f;
                float e1 = (c0 + 1 < vl) ? ex2f(sc[nt][1]) : 0.f;
                float e2 = (c0     < vl) ? ex2f(sc[nt][2]) : 0.f;
                float e3 = (c0 + 1 < vl) ? ex2f(sc[nt][3]) : 0.f;
                lsum0 += e0 + e1;
                lsum1 += e2 + e3;
                int j = nt >> 1, hf = (nt & 1) * 2;
                phi[j][hf + 0] = cvt2h(e0, e1);
                phi[j][hf + 1] = cvt2h(e2, e3);
            }
        }

        // ---- O += ph * vh : single pass ----
        #pragma unroll
        for (int nt = 0; nt < 8; nt++){
            uint32_t vh[8];
            uint32_t base = (uint32_t)ln * SKB + (uint32_t)nt * 16;
            ldsm4t(vh + 0, sb + SM_VH + base);
            ldsm4t(vh + 4, sb + SM_VH + base + 32u * SKB);
            #pragma unroll
            for (int ks = 0; ks < 4; ks++)
                mma16816(oc[nt], phi[ks], vh[2*ks], vh[2*ks+1]);
        }
    }

    // ---- reduce row sums across quads ----
    lsum0 += __shfl_xor_sync(0xffffffffu, lsum0, 1);
    lsum0 += __shfl_xor_sync(0xffffffffu, lsum0, 2);
    lsum1 += __shfl_xor_sync(0xffffffffu, lsum1, 1);
    lsum1 += __shfl_xor_sync(0xffffffffu, lsum1, 2);

    // ---- write unnormalized partials to scratch ----
    const int rg0 = b * Lq + q0 + 16*w + g;
    float* Op0 = g_Opart + ((size_t)c * R + rg0) * DH;
    float* Op1 = Op0 + (size_t)8 * DH;
    if (tg == 0){
        g_lpart[(size_t)c * R + rg0]     = lsum0;
        g_lpart[(size_t)c * R + rg0 + 8] = lsum1;
    }
    #pragma unroll
    for (int nt = 0; nt < 8; nt++){
        float2 a0, a1;
        a0.x = oc[nt][0]; a0.y = oc[nt][1];
        a1.x = oc[nt][2]; a1.y = oc[nt][3];
        *(float2*)(Op0 + nt*8 + 2*tg) = a0;
        *(float2*)(Op1 + nt*8 + 2*tg) = a1;
    }
}

// ---------------- Phase 2: combine chunk partials + normalize ----------------
// Unrolled predicated loads: MLP=4 kept, inactive-chunk traffic skipped.
__global__ __launch_bounds__(256, 8)
void fa_combine_kernel(const int* __restrict__ vlen, float* __restrict__ O,
                       int Lq, int Lk, int B, int ck)
{
    const int idx = blockIdx.x * blockDim.x + threadIdx.x;
    const int total = B * Lq * (DH / 4);
    if (idx >= total) return;

    const int rd = idx >> 4;
    const int d4 = idx & 15;
    const int b  = rd / Lq;
    const int R  = B * Lq;

    int vl = vlen[b];
    if (vl < 1) vl = 1;
    if (vl > Lk) vl = Lk;
    const int nact = (vl + ck - 1) / ck;

    float4 p[NCH_MAX];
    float  lp[NCH_MAX];
    #pragma unroll
    for (int c = 0; c < NCH_MAX; c++){
        if (c < nact){
            p[c]  = *(const float4*)(g_Opart + ((size_t)c * R + rd) * DH + d4 * 4);
            lp[c] = g_lpart[(size_t)c * R + rd];
        } else {
            p[c]  = make_float4(0.f, 0.f, 0.f, 0.f);
            lp[c] = 0.f;
        }
    }
    float4 acc = make_float4(0.f, 0.f, 0.f, 0.f);
    float l = 0.f;
    #pragma unroll
    for (int c = 0; c < NCH_MAX; c++){
        acc.x += p[c].x; acc.y += p[c].y;
        acc.z += p[c].z; acc.w += p[c].w;
        l     += lp[c];
    }
    const float inv = 1.f / l;
    acc.x *= inv; acc.y *= inv; acc.z *= inv; acc.w *= inv;
    *(float4*)(O + (size_t)rd * DH + d4 * 4) = acc;
}

extern "C" void kernel_launch(void* const* d_in, const int* in_sizes, int n_in,
                              void* d_out, int out_size)
{
    const float* Q  = (const float*)d_in[0];
    const float* K  = (const float*)d_in[1];
    const float* V  = (const float*)d_in[2];
    const int*   vl = (const int*)d_in[3];
    float*       O  = (float*)d_out;

    const int B  = in_sizes[3];
    const int Lq = in_sizes[0] / (B * DH);
    const int Lk = in_sizes[1] / (B * DH);

    int ck = ((Lk + NCH_MAX * BN - 1) / (NCH_MAX * BN)) * BN;
    if (ck < BN) ck = BN;
    const int nch = (Lk + ck - 1) / ck;

    // Phase 0: K/V fp32 -> fp16 (once)
    const int n8 = (B * Lk * DH) / 8;
    fa_cvt_kernel<<<(n8 + 255) / 256, 256>>>(K, V, n8);

    cudaFuncSetAttribute(fa_part_kernel,
                         cudaFuncAttributeMaxDynamicSharedMemorySize, SM_TOTAL);

    dim3 grid1(Lq / BM, B, nch);
    fa_part_kernel<<<grid1, 256, SM_TOTAL>>>(Q, vl, Lq, Lk, ck);

    const int total = B * Lq * (DH / 4);
    fa_combine_kernel<<<(total + 255) / 256, 256>>>(vl, O, Lq, Lk, B, ck);
}

// round 12
// speedup vs baseline: 1.4097x; 1.0667x over previous
#include <cuda_runtime.h>
#include <cuda_fp16.h>
#include <cstdint>

#define DH 64
#define BM 128
#define BN 64
#define SKB 144          // smem row stride bytes (72 fp16) -> ldmatrix conflict-free

#define SM_QH  0
#define SM_KH  (BM*SKB)               // 18432
#define SM_VH  (SM_KH + BN*SKB)       // 27648
#define SM_TOTAL (SM_VH + BN*SKB)     // 36864 B -> 2 CTAs/SM

#define MAXROWS 16384                 // max B*Lq and B*Lk
#define NCH_MAX 4

__device__ float g_Opart[(size_t)NCH_MAX * MAXROWS * DH];
__device__ float g_lpart[(size_t)NCH_MAX * MAXROWS];
// fp16 copies of K and V (filled by prepass, read by phase 1)
__device__ uint4 g_Kh[(size_t)MAXROWS * DH / 8];
__device__ uint4 g_Vh[(size_t)MAXROWS * DH / 8];

static __device__ __forceinline__ uint32_t smem_u32(const void* p){
    uint32_t a;
    asm("{ .reg .u64 t; cvta.to.shared.u64 t, %1; cvt.u32.u64 %0, t; }" : "=r"(a) : "l"(p));
    return a;
}
static __device__ __forceinline__ float ex2f(float x){
    float r;
    asm("ex2.approx.f32 %0, %1;" : "=f"(r) : "f"(x));
    return r;
}
static __device__ __forceinline__ uint32_t cvt2h(float a, float b){
    __half2 h = __floats2half2_rn(a, b);
    return *reinterpret_cast<uint32_t*>(&h);
}
static __device__ __forceinline__ void cvtH8(const float* f, uint4& out){
    out = make_uint4(cvt2h(f[0], f[1]), cvt2h(f[2], f[3]),
                     cvt2h(f[4], f[5]), cvt2h(f[6], f[7]));
}
static __device__ __forceinline__ void ldsm4(uint32_t* r, uint32_t a){
    asm volatile("ldmatrix.sync.aligned.m8n8.x4.shared.b16 {%0,%1,%2,%3}, [%4];"
                 : "=r"(r[0]), "=r"(r[1]), "=r"(r[2]), "=r"(r[3]) : "r"(a));
}
static __device__ __forceinline__ void ldsm4t(uint32_t* r, uint32_t a){
    asm volatile("ldmatrix.sync.aligned.m8n8.x4.trans.shared.b16 {%0,%1,%2,%3}, [%4];"
                 : "=r"(r[0]), "=r"(r[1]), "=r"(r[2]), "=r"(r[3]) : "r"(a));
}
static __device__ __forceinline__ void mma16816(float* d, const uint32_t* a, uint32_t b0, uint32_t b1){
    asm volatile("mma.sync.aligned.m16n8k16.row.col.f32.f16.f16.f32 "
                 "{%0,%1,%2,%3}, {%4,%5,%6,%7}, {%8,%9}, {%0,%1,%2,%3};"
                 : "+f"(d[0]), "+f"(d[1]), "+f"(d[2]), "+f"(d[3])
                 : "r"(a[0]), "r"(a[1]), "r"(a[2]), "r"(a[3]), "r"(b0), "r"(b1));
}

// ---------------- Phase 0: convert K,V fp32 -> fp16 once ----------------
// K and V handled by disjoint thread ranges: 2x parallelism vs R11.
__global__ __launch_bounds__(256, 8)
void fa_cvt_kernel(const float* __restrict__ K, const float* __restrict__ V, int n8)
{
    const int i = blockIdx.x * blockDim.x + threadIdx.x;
    if (i >= 2 * n8) return;
    const bool isK = (i < n8);
    const int  j   = isK ? i : i - n8;
    const float* src = isK ? K : V;
    float f[8];
    *(float4*)(f)     = *(const float4*)(src + (size_t)j * 8);
    *(float4*)(f + 4) = *(const float4*)(src + (size_t)j * 8 + 4);
    uint4 u; cvtH8(f, u);
    (isK ? g_Kh : g_Vh)[j] = u;
}

// ---------------- Phase 1: partial attention over one key chunk ----------------
__global__ __launch_bounds__(256, 2)
void fa_part_kernel(const float* __restrict__ Q, const int* __restrict__ vlen,
                    int Lq, int Lk, int ck)
{
    extern __shared__ char smem[];
    const uint32_t sb = smem_u32(smem);
    const int t  = threadIdx.x;
    const int w  = t >> 5;
    const int ln = t & 31;
    const int g  = ln >> 2;
    const int tg = ln & 3;
    const int b  = blockIdx.y;
    const int q0 = blockIdx.x * BM;
    const int c  = blockIdx.z;

    int vl = vlen[b];
    if (vl < 1) vl = 1;
    if (vl > Lk) vl = Lk;

    const int cstart = c * ck;
    if (cstart >= vl) return;
    const int kend   = (cstart + ck < vl) ? cstart + ck : vl;
    const int ntiles = (kend - cstart + BN - 1) / BN;

    const int B_ = gridDim.y;
    const int R  = B_ * Lq;

    const float* Qb = Q + ((size_t)b * Lq + q0) * DH;
    const uint4* Kb = g_Kh + ((size_t)b * Lk + cstart) * (DH / 8);
    const uint4* Vb = g_Vh + ((size_t)b * Lk + cstart) * (DH / 8);

    // ---- Q -> smem, pre-scaled by log2e/sqrt(d), single fp16 ----
    {
        int r = t >> 1, h = t & 1;
        const float* qp = Qb + (size_t)r * DH + h * 32;
        float f[32];
        #pragma unroll
        for (int i = 0; i < 8; i++) *(float4*)(f + 4*i) = *(const float4*)(qp + 4*i);
        #pragma unroll
        for (int i = 0; i < 32; i++) f[i] *= 0.18033688f;   // 1.4426950f / 8
        #pragma unroll
        for (int cc = 0; cc < 4; cc++){
            uint4 u; cvtH8(f + 8*cc, u);
            *(uint4*)(smem + SM_QH + r * SKB + (h*4 + cc) * 16) = u;
        }
    }
    __syncthreads();

    // ---- Q A-fragments (registers for whole kernel) ----
    uint32_t qh[4][4];
    {
        uint32_t rowoff = (uint32_t)(16*w + (ln & 15)) * SKB + (uint32_t)(ln >> 4) * 16;
        #pragma unroll
        for (int ks = 0; ks < 4; ks++)
            ldsm4(qh[ks], sb + SM_QH + rowoff + ks * 32);
    }

    float oc[8][4];
    #pragma unroll
    for (int nt = 0; nt < 8; nt++)
        #pragma unroll
        for (int j = 0; j < 4; j++) oc[nt][j] = 0.f;
    float lsum0 = 0.f, lsum1 = 0.f;

    // ---- prefetch tile 0: thread owns 32 halfs of K and of V ----
    const int r4 = t >> 2, qq = t & 3;
    uint4 ku[2], vu[2];
    {
        const uint4* kp = Kb + (size_t)r4 * (DH / 8) + qq * 2;
        const uint4* vp = Vb + (size_t)r4 * (DH / 8) + qq * 2;
        ku[0] = kp[0]; ku[1] = kp[1];
        vu[0] = vp[0]; vu[1] = vp[1];
    }

    for (int kt = 0; kt < ntiles; kt++){
        const int n0g = cstart + kt * BN;

        __syncthreads();   // prev tile's ldmatrix reads done
        {
            int off = r4 * SKB + qq * 32;
            *(uint4*)(smem + SM_KH + off)      = ku[0];
            *(uint4*)(smem + SM_KH + off + 16) = ku[1];
            *(uint4*)(smem + SM_VH + off)      = vu[0];
            *(uint4*)(smem + SM_VH + off + 16) = vu[1];
        }
        __syncthreads();

        // ---- prefetch next tile ----
        if (kt + 1 < ntiles){
            const uint4* kp = Kb + (size_t)((kt+1)*BN + r4) * (DH / 8) + qq * 2;
            const uint4* vp = Vb + (size_t)((kt+1)*BN + r4) * (DH / 8) + qq * 2;
            ku[0] = kp[0]; ku[1] = kp[1];
            vu[0] = vp[0]; vu[1] = vp[1];
        }

        // ---- fused S-MMA + epilogue per nt (keeps sc live range at 4 regs) ----
        uint32_t phi[4][4];
        const bool full = (n0g + BN <= vl);
        #pragma unroll
        for (int nt = 0; nt < 8; nt++){
            float sc4[4] = {0.f, 0.f, 0.f, 0.f};
            uint32_t kh[8];
            uint32_t base = (uint32_t)(8*nt + (ln & 7)) * SKB
                          + (uint32_t)((ln >> 3) & 1) * 16
                          + (uint32_t)(ln >> 4) * 32;
            ldsm4(kh + 0, sb + SM_KH + base);
            ldsm4(kh + 4, sb + SM_KH + base + 64);
            #pragma unroll
            for (int ks = 0; ks < 4; ks++)
                mma16816(sc4, qh[ks], kh[2*ks], kh[2*ks+1]);

            float e0, e1, e2, e3;
            if (full){
                e0 = ex2f(sc4[0]); e1 = ex2f(sc4[1]);
                e2 = ex2f(sc4[2]); e3 = ex2f(sc4[3]);
            } else {
                int c0 = n0g + nt*8 + 2*tg;
                e0 = (c0     < vl) ? ex2f(sc4[0]) : 0.f;
                e1 = (c0 + 1 < vl) ? ex2f(sc4[1]) : 0.f;
                e2 = (c0     < vl) ? ex2f(sc4[2]) : 0.f;
                e3 = (c0 + 1 < vl) ? ex2f(sc4[3]) : 0.f;
            }
            lsum0 += e0 + e1;
            lsum1 += e2 + e3;
            int j = nt >> 1, hf = (nt & 1) * 2;
            phi[j][hf + 0] = cvt2h(e0, e1);
            phi[j][hf + 1] = cvt2h(e2, e3);
        }

        // ---- O += ph * vh : single pass ----
        #pragma unroll
        for (int nt = 0; nt < 8; nt++){
            uint32_t vh[8];
            uint32_t base = (uint32_t)ln * SKB + (uint32_t)nt * 16;
            ldsm4t(vh + 0, sb + SM_VH + base);
            ldsm4t(vh + 4, sb + SM_VH + base + 32u * SKB);
            #pragma unroll
            for (int ks = 0; ks < 4; ks++)
                mma16816(oc[nt], phi[ks], vh[2*ks], vh[2*ks+1]);
        }
    }

    // ---- reduce row sums across quads ----
    lsum0 += __shfl_xor_sync(0xffffffffu, lsum0, 1);
    lsum0 += __shfl_xor_sync(0xffffffffu, lsum0, 2);
    lsum1 += __shfl_xor_sync(0xffffffffu, lsum1, 1);
    lsum1 += __shfl_xor_sync(0xffffffffu, lsum1, 2);

    // ---- write unnormalized partials to scratch ----
    const int rg0 = b * Lq + q0 + 16*w + g;
    float* Op0 = g_Opart + ((size_t)c * R + rg0) * DH;
    float* Op1 = Op0 + (size_t)8 * DH;
    if (tg == 0){
        g_lpart[(size_t)c * R + rg0]     = lsum0;
        g_lpart[(size_t)c * R + rg0 + 8] = lsum1;
    }
    #pragma unroll
    for (int nt = 0; nt < 8; nt++){
        float2 a0, a1;
        a0.x = oc[nt][0]; a0.y = oc[nt][1];
        a1.x = oc[nt][2]; a1.y = oc[nt][3];
        *(float2*)(Op0 + nt*8 + 2*tg) = a0;
        *(float2*)(Op1 + nt*8 + 2*tg) = a1;
    }
}

// ---------------- Phase 2: combine chunk partials + normalize ----------------
__global__ __launch_bounds__(256, 8)
void fa_combine_kernel(const int* __restrict__ vlen, float* __restrict__ O,
                       int Lq, int Lk, int B, int ck)
{
    const int idx = blockIdx.x * blockDim.x + threadIdx.x;
    const int total = B * Lq * (DH / 4);
    if (idx >= total) return;

    const int rd = idx >> 4;
    const int d4 = idx & 15;
    const int b  = rd / Lq;
    const int R  = B * Lq;

    int vl = vlen[b];
    if (vl < 1) vl = 1;
    if (vl > Lk) vl = Lk;
    const int nact = (vl + ck - 1) / ck;

    float4 p[NCH_MAX];
    float  lp[NCH_MAX];
    #pragma unroll
    for (int c = 0; c < NCH_MAX; c++){
        if (c < nact){
            p[c]  = *(const float4*)(g_Opart + ((size_t)c * R + rd) * DH + d4 * 4);
            lp[c] = g_lpart[(size_t)c * R + rd];
        } else {
            p[c]  = make_float4(0.f, 0.f, 0.f, 0.f);
            lp[c] = 0.f;
        }
    }
    float4 acc = make_float4(0.f, 0.f, 0.f, 0.f);
    float l = 0.f;
    #pragma unroll
    for (int c = 0; c < NCH_MAX; c++){
        acc.x += p[c].x; acc.y += p[c].y;
        acc.z += p[c].z; acc.w += p[c].w;
        l     += lp[c];
    }
    const float inv = 1.f / l;
    acc.x *= inv; acc.y *= inv; acc.z *= inv; acc.w *= inv;
    *(float4*)(O + (size_t)rd * DH + d4 * 4) = acc;
}

extern "C" void kernel_launch(void* const* d_in, const int* in_sizes, int n_in,
                              void* d_out, int out_size)
{
    const float* Q  = (const float*)d_in[0];
    const float* K  = (const float*)d_in[1];
    const float* V  = (const float*)d_in[2];
    const int*   vl = (const int*)d_in[3];
    float*       O  = (float*)d_out;

    const int B  = in_sizes[3];
    const int Lq = in_sizes[0] / (B * DH);
    const int Lk = in_sizes[1] / (B * DH);

    int ck = ((Lk + NCH_MAX * BN - 1) / (NCH_MAX * BN)) * BN;
    if (ck < BN) ck = BN;
    const int nch = (Lk + ck - 1) / ck;

    const int n8 = (B * Lk * DH) / 8;
    fa_cvt_kernel<<<(2 * n8 + 255) / 256, 256>>>(K, V, n8);

    cudaFuncSetAttribute(fa_part_kernel,
                         cudaFuncAttributeMaxDynamicSharedMemorySize, SM_TOTAL);

    dim3 grid1(Lq / BM, B, nch);
    fa_part_kernel<<<grid1, 256, SM_TOTAL>>>(Q, vl, Lq, Lk, ck);

    const int total = B * Lq * (DH / 4);
    fa_combine_kernel<<<(total + 255) / 256, 256>>>(vl, O, Lq, Lk, B, ck);
}